// round 6
// baseline (speedup 1.0000x reference)
#include <cuda_runtime.h>
#include <cstdint>
#include <cstddef>

#define Bb 2
#define Ss 2048
#define Ee 1024
#define Hh 16
#define Dd 64
#define Mm (Bb*Ss)

// ---------------------------------------------------------------------------
// Scratch
// ---------------------------------------------------------------------------
__device__ float g_q[Mm * Ee];
__device__ float g_k[Mm * Ee];
__device__ float g_v[Mm * Ee];
__device__ float g_g[Bb * Hh * Ss];

// ---------------------------------------------------------------------------
// Helpers (family-agnostic PTX only: cp.async, ldmatrix, mma.sync — sm_80+)
// ---------------------------------------------------------------------------
__device__ __forceinline__ uint32_t smem_u32(const void* p) {
    uint32_t a;
    asm("{ .reg .u64 t; cvta.to.shared.u64 t, %1; cvt.u32.u64 %0, t; }"
        : "=r"(a) : "l"(p));
    return a;
}
__device__ __forceinline__ void cpa16(uint32_t s, const void* g) {
    asm volatile("cp.async.cg.shared.global [%0], [%1], 16;" :: "r"(s), "l"(g));
}
__device__ __forceinline__ void cpa_commit() {
    asm volatile("cp.async.commit_group;" ::: "memory");
}
template<int N> __device__ __forceinline__ void cpa_wait() {
    asm volatile("cp.async.wait_group %0;" :: "n"(N) : "memory");
}
__device__ __forceinline__ void ldsm4(uint32_t& r0, uint32_t& r1,
                                      uint32_t& r2, uint32_t& r3, uint32_t addr) {
    asm volatile("ldmatrix.sync.aligned.m8n8.x4.shared.b16 {%0,%1,%2,%3}, [%4];"
                 : "=r"(r0), "=r"(r1), "=r"(r2), "=r"(r3) : "r"(addr));
}
// round-to-nearest fp32 -> tf32 (kills the RZ truncation bias of mma.sync)
__device__ __forceinline__ uint32_t rna(uint32_t x) {
    uint32_t y;
    asm("cvt.rna.tf32.f32 %0, %1;" : "=r"(y) : "r"(x));
    return y;
}
__device__ __forceinline__ void mma8(float* c, const uint32_t* a,
                                     uint32_t b0, uint32_t b1) {
    asm volatile(
        "mma.sync.aligned.m16n8k8.row.col.f32.tf32.tf32.f32 "
        "{%0,%1,%2,%3}, {%4,%5,%6,%7}, {%8,%9}, {%0,%1,%2,%3};"
        : "+f"(c[0]), "+f"(c[1]), "+f"(c[2]), "+f"(c[3])
        : "r"(a[0]), "r"(a[1]), "r"(a[2]), "r"(a[3]), "r"(b0), "r"(b1));
}

// FFMA-only exp
__device__ __forceinline__ float fast_exp(float x) {
    float t = x * 1.4426950408889634f;
    int   e = __float2int_rn(t);
    float f = t - (float)e;
    float p = 0.0013333558146428443f;
    p = fmaf(p, f, 0.009618129842126066f);
    p = fmaf(p, f, 0.05550410866482158f);
    p = fmaf(p, f, 0.2402265069591007f);
    p = fmaf(p, f, 0.6931471805599453f);
    p = fmaf(p, f, 1.0f);
    return p * __int_as_float((e + 127) << 23);
}

// ---------------------------------------------------------------------------
// Dense GEMM core: C[128x128] = A[128xK] @ Bw[128xK]^T (+Resid)
// 512 threads (16 warps, 4x4). Warp tile 32x32. BK=32, 3-stage cp.async.
// SMEM stage: A 128x32 (16KB, swizzled) | B 128x32 (16KB).
// ---------------------------------------------------------------------------
template<bool RES>
__device__ __forceinline__ void gemm_core(const float* __restrict__ A,
                                          const float* __restrict__ Bw,
                                          float* __restrict__ C,
                                          const float* __restrict__ Resid,
                                          int m0, int n0, char* dsm)
{
    const uint32_t stg = smem_u32(dsm);
    const int tid = threadIdx.x;
    const int wid = tid >> 5, lane = tid & 31;
    const int wr = wid >> 2, wc = wid & 3;

    auto load_stage = [&](int kb) {
        uint32_t s = stg + (uint32_t)(kb % 3) * 32768u;
        int k0 = kb * 32;
#pragma unroll
        for (int i = 0; i < 4; i++) {
            int j     = tid + i * 512;     // 0..2047
            int which = j >> 10;           // 0:A 1:B
            int idx   = j & 1023;
            int r     = idx >> 3;          // 0..127
            int ch    = idx & 7;           // 16B chunk
            uint32_t dst = s + (uint32_t)which * 16384u
                         + (uint32_t)r * 128u + ((uint32_t)(ch ^ (r & 7)) << 4);
            const float* src = which ? &Bw[(size_t)(n0 + r) * Ee + k0 + ch * 4]
                                     : &A [(size_t)(m0 + r) * Ee + k0 + ch * 4];
            cpa16(dst, src);
        }
        cpa_commit();
    };

    float acc[2][4][4];
#pragma unroll
    for (int i = 0; i < 2; i++)
#pragma unroll
        for (int j = 0; j < 4; j++)
#pragma unroll
            for (int k = 0; k < 4; k++) acc[i][j][k] = 0.f;

    load_stage(0); load_stage(1);

    const int rA = wr * 32 + (lane & 15);                         // + mi*16
    const int cAbit = lane >> 4;                                  // 0/1
    const int rB = wc * 32 + (lane & 7) + ((lane >> 4) << 3);     // + njp*16
    const int cBbit = (lane >> 3) & 1;

    for (int kb = 0; kb < 32; ++kb) {
        if (kb + 2 < 32) cpa_wait<1>(); else cpa_wait<0>();
        __syncthreads();
        if (kb + 2 < 32) load_stage(kb + 2);

        uint32_t As = stg + (uint32_t)(kb % 3) * 32768u;
        uint32_t Bs = As + 16384u;
#pragma unroll
        for (int s8 = 0; s8 < 4; ++s8) {
            uint32_t a[2][4];
#pragma unroll
            for (int mi = 0; mi < 2; mi++) {
                int row = rA + mi * 16;
                int ch  = 2 * s8 + cAbit;
                uint32_t addr = As + (uint32_t)row * 128u
                              + ((uint32_t)(ch ^ (row & 7)) << 4);
                ldsm4(a[mi][0], a[mi][1], a[mi][2], a[mi][3], addr);
#pragma unroll
                for (int q = 0; q < 4; q++) a[mi][q] = rna(a[mi][q]);
            }
            uint32_t b[2][4];
#pragma unroll
            for (int njp = 0; njp < 2; njp++) {
                int row = rB + njp * 16;
                int ch  = 2 * s8 + cBbit;
                uint32_t addr = Bs + (uint32_t)row * 128u
                              + ((uint32_t)(ch ^ (row & 7)) << 4);
                ldsm4(b[njp][0], b[njp][1], b[njp][2], b[njp][3], addr);
#pragma unroll
                for (int q = 0; q < 4; q++) b[njp][q] = rna(b[njp][q]);
            }
#pragma unroll
            for (int mi = 0; mi < 2; mi++)
#pragma unroll
                for (int nj = 0; nj < 4; nj++)
                    mma8(acc[mi][nj], a[mi],
                         b[nj >> 1][(nj & 1) * 2], b[nj >> 1][(nj & 1) * 2 + 1]);
        }
    }

    // epilogue: c0:(g,2t) c1:(g,2t+1) c2:(g+8,2t) c3:(g+8,2t+1)
#pragma unroll
    for (int mi = 0; mi < 2; mi++) {
        int r0 = m0 + wr * 32 + mi * 16 + (lane >> 2);
#pragma unroll
        for (int nj = 0; nj < 4; nj++) {
            int c0 = n0 + wc * 32 + nj * 8 + 2 * (lane & 3);
            float2 v0 = {acc[mi][nj][0], acc[mi][nj][1]};
            float2 v1 = {acc[mi][nj][2], acc[mi][nj][3]};
            if (RES) {
                float2 a0 = *(const float2*)&Resid[(size_t)r0 * Ee + c0];
                float2 a1 = *(const float2*)&Resid[(size_t)(r0 + 8) * Ee + c0];
                v0.x += a0.x; v0.y += a0.y; v1.x += a1.x; v1.y += a1.y;
            }
            *(float2*)&C[(size_t)r0 * Ee + c0]       = v0;
            *(float2*)&C[(size_t)(r0 + 8) * Ee + c0] = v1;
        }
    }
}

__global__ void __launch_bounds__(512, 1)
tc_qkv(const float* __restrict__ X, const float* __restrict__ Wq,
       const float* __restrict__ Wk, const float* __restrict__ Wv)
{
    extern __shared__ char dsm[];
    const float* W = (blockIdx.z == 0) ? Wq : (blockIdx.z == 1) ? Wk : Wv;
    float*       C = (blockIdx.z == 0) ? g_q : (blockIdx.z == 1) ? g_k : g_v;
    gemm_core<false>(X, W, C, nullptr, blockIdx.y * 128, blockIdx.x * 128, dsm);
}

__global__ void __launch_bounds__(512, 1)
tc_out(const float* __restrict__ Wo, float* __restrict__ Out)
{
    extern __shared__ char dsm[];
    gemm_core<true>(g_q, Wo, Out, g_v, blockIdx.y * 128, blockIdx.x * 128, dsm);
}

// ---------------------------------------------------------------------------
// Score pass: per (b,h,qtile=128 rows): for each causal kt tile compute
// S = Q[128x64] @ K[128x64]^T via mma, exp+mask in registers, row sums
// accumulated across tiles. Gate g = diag / rowsum.
// 512 threads, warp tile 32x32. SMEM: Q 32KB + 3 K stages x 32KB + reduce.
// ---------------------------------------------------------------------------
__global__ void __launch_bounds__(512, 1)
tc_score()
{
    extern __shared__ char dsm[];
    const uint32_t base = smem_u32(dsm);
    const uint32_t Qs = base;
    const uint32_t Ks = base + 32768u;
    float* sSum  = (float*)(dsm + 131072);
    float* sDiag = (float*)(dsm + 131072 + 512);

    const int qt = blockIdx.x, h = blockIdx.y, b = blockIdx.z;
    const int tid = threadIdx.x;
    const int wid = tid >> 5, lane = tid & 31;
    const int wr = wid >> 2, wc = wid & 3;

    auto load_q = [&]() {
#pragma unroll
        for (int i = 0; i < 4; i++) {
            int j  = tid + i * 512;     // 0..2047
            int r  = j >> 4;            // 0..127
            int ch = j & 15;            // 16 chunks (64 floats/row)
            uint32_t dst = Qs + (uint32_t)r * 256u + ((uint32_t)(ch ^ (r & 7)) << 4);
            cpa16(dst, &g_q[(size_t)(b * Ss + qt * 128 + r) * Ee + h * Dd + ch * 4]);
        }
    };
    auto load_k = [&](int kt, int slot) {
        uint32_t s = Ks + (uint32_t)slot * 32768u;
#pragma unroll
        for (int i = 0; i < 4; i++) {
            int j  = tid + i * 512;
            int r  = j >> 4;
            int ch = j & 15;
            uint32_t dst = s + (uint32_t)r * 256u + ((uint32_t)(ch ^ (r & 7)) << 4);
            cpa16(dst, &g_k[(size_t)(b * Ss + kt * 128 + r) * Ee + h * Dd + ch * 4]);
        }
    };

    load_q(); load_k(0, 0); cpa_commit();
    if (qt >= 1) { load_k(1, 1); cpa_commit(); }

    if (tid < 128) { sSum[tid] = 0.f; sDiag[tid] = 0.f; }

    float rs[4], dv[4];
#pragma unroll
    for (int k = 0; k < 4; k++) { rs[k] = 0.f; dv[k] = 0.f; }

    const int rA = wr * 32 + (lane & 15);
    const int cAbit = lane >> 4;
    const int rB = wc * 32 + (lane & 7) + ((lane >> 4) << 3);
    const int cBbit = (lane >> 3) & 1;

    for (int kt = 0; kt <= qt; ++kt) {
        if (kt == qt) cpa_wait<0>(); else cpa_wait<1>();
        __syncthreads();
        if (kt + 2 <= qt) { load_k(kt + 2, (kt + 2) % 3); cpa_commit(); }

        float acc[2][4][4];
#pragma unroll
        for (int i = 0; i < 2; i++)
#pragma unroll
            for (int j = 0; j < 4; j++)
#pragma unroll
                for (int k = 0; k < 4; k++) acc[i][j][k] = 0.f;

        uint32_t Ksl = Ks + (uint32_t)(kt % 3) * 32768u;
#pragma unroll
        for (int s8 = 0; s8 < 8; ++s8) {
            uint32_t a[2][4];
#pragma unroll
            for (int mi = 0; mi < 2; mi++) {
                int row = rA + mi * 16;
                int ch  = 2 * s8 + cAbit;
                uint32_t addr = Qs + (uint32_t)row * 256u
                              + ((uint32_t)(ch ^ (row & 7)) << 4);
                ldsm4(a[mi][0], a[mi][1], a[mi][2], a[mi][3], addr);
#pragma unroll
                for (int q = 0; q < 4; q++) a[mi][q] = rna(a[mi][q]);
            }
            uint32_t bfr[2][4];
#pragma unroll
            for (int njp = 0; njp < 2; njp++) {
                int row = rB + njp * 16;
                int ch  = 2 * s8 + cBbit;
                uint32_t addr = Ksl + (uint32_t)row * 256u
                              + ((uint32_t)(ch ^ (row & 7)) << 4);
                ldsm4(bfr[njp][0], bfr[njp][1], bfr[njp][2], bfr[njp][3], addr);
#pragma unroll
                for (int q = 0; q < 4; q++) bfr[njp][q] = rna(bfr[njp][q]);
            }
#pragma unroll
            for (int mi = 0; mi < 2; mi++)
#pragma unroll
                for (int nj = 0; nj < 4; nj++)
                    mma8(acc[mi][nj], a[mi],
                         bfr[nj >> 1][(nj & 1) * 2], bfr[nj >> 1][(nj & 1) * 2 + 1]);
        }

        const bool dt = (kt == qt);
#pragma unroll
        for (int mi = 0; mi < 2; mi++) {
            int il0 = wr * 32 + mi * 16 + (lane >> 2);
#pragma unroll
            for (int nj = 0; nj < 4; nj++) {
                int jl = wc * 32 + nj * 8 + 2 * (lane & 3);
#pragma unroll
                for (int q = 0; q < 4; q++) {
                    int il = il0 + (q >> 1) * 8;
                    int j  = jl  + (q & 1);
                    float e = fast_exp(acc[mi][nj][q] * 0.03125f);
                    if (dt) {
                        if (j > il)  e = 0.f;
                        if (j == il) dv[mi * 2 + (q >> 1)] = e;
                    }
                    rs[mi * 2 + (q >> 1)] += e;
                }
            }
        }
    }

    // quad reduce (lanes in a quad share rows)
#pragma unroll
    for (int k = 0; k < 4; k++) {
        rs[k] += __shfl_xor_sync(0xffffffffu, rs[k], 1);
        rs[k] += __shfl_xor_sync(0xffffffffu, rs[k], 2);
        dv[k] += __shfl_xor_sync(0xffffffffu, dv[k], 1);
        dv[k] += __shfl_xor_sync(0xffffffffu, dv[k], 2);
    }
    if ((lane & 3) == 0) {
#pragma unroll
        for (int k = 0; k < 4; k++) {
            int row = wr * 32 + (k >> 1) * 16 + (k & 1) * 8 + (lane >> 2);
            atomicAdd(&sSum[row], rs[k]);
            atomicAdd(&sDiag[row], dv[k]);
        }
    }
    __syncthreads();
    if (tid < 128)
        g_g[((size_t)b * Hh + h) * Ss + qt * 128 + tid] = sDiag[tid] / sSum[tid];
}

// ---------------------------------------------------------------------------
// gv = g ⊙ v  (into g_q; q is dead after the score pass)
// ---------------------------------------------------------------------------
__global__ void __launch_bounds__(256) gv_prep()
{
    int row = blockIdx.x;
    int tid = threadIdx.x;
    int b = row >> 11, s = row & 2047;
    int h = tid >> 4;
    float gval = g_g[((size_t)(b * Hh + h)) * Ss + s];
    float4 v = *(const float4*)&g_v[(size_t)row * Ee + tid * 4];
    v.x *= gval; v.y *= gval; v.z *= gval; v.w *= gval;
    *(float4*)&g_q[(size_t)row * Ee + tid * 4] = v;
}

// ---------------------------------------------------------------------------
extern "C" void kernel_launch(void* const* d_in, const int* in_sizes, int n_in,
                              void* d_out, int out_size)
{
    const float* x  = (const float*)d_in[0];
    const float* wq = (const float*)d_in[1];
    const float* wk = (const float*)d_in[2];
    const float* wv = (const float*)d_in[3];
    const float* wo = (const float*)d_in[4];
    float* out = (float*)d_out;

    const int SMEM_GEMM  = 3 * 32768;            // 98304
    const int SMEM_SCORE = 4 * 32768 + 1024;     // Q + 3 K stages + reduce

    cudaFuncSetAttribute(tc_qkv,   cudaFuncAttributeMaxDynamicSharedMemorySize, SMEM_GEMM);
    cudaFuncSetAttribute(tc_out,   cudaFuncAttributeMaxDynamicSharedMemorySize, SMEM_GEMM);
    cudaFuncSetAttribute(tc_score, cudaFuncAttributeMaxDynamicSharedMemorySize, SMEM_SCORE);

    tc_qkv<<<dim3(Ee / 128, Mm / 128, 3), 512, SMEM_GEMM>>>(x, wq, wk, wv);
    tc_score<<<dim3(Ss / 128, Hh, Bb), 512, SMEM_SCORE>>>();
    gv_prep<<<Mm, 256>>>();
    tc_out<<<dim3(Ee / 128, Mm / 128), 512, SMEM_GEMM>>>(wo, out);
}

// round 7
// speedup vs baseline: 1.9044x; 1.9044x over previous
#include <cuda_runtime.h>
#include <cuda_fp16.h>
#include <cstdint>
#include <cstddef>

#define Bb 2
#define Ss 2048
#define Ee 1024
#define Hh 16
#define Dd 64
#define Mm (Bb*Ss)

// ---------------------------------------------------------------------------
// Scratch (fp16 operand chain + fp32 v for residual)
// ---------------------------------------------------------------------------
__device__ __half g_xh [Mm * Ee];     // x in fp16
__device__ __half g_wqh[Ee * Ee];
__device__ __half g_wkh[Ee * Ee];
__device__ __half g_wvh[Ee * Ee];
__device__ __half g_woh[Ee * Ee];
__device__ __half g_qh [Mm * Ee];     // q (fp16)
__device__ __half g_kh [Mm * Ee];     // k (fp16)
__device__ __half g_avh[Mm * Ee];     // g ⊙ v (fp16)
__device__ float  g_v  [Mm * Ee];     // v (fp32, residual)
__device__ float  g_g  [Bb * Hh * Ss];

// ---------------------------------------------------------------------------
// Helpers (family-agnostic PTX: cp.async, ldmatrix, mma.sync — sm_80+)
// ---------------------------------------------------------------------------
__device__ __forceinline__ uint32_t smem_u32(const void* p) {
    uint32_t a;
    asm("{ .reg .u64 t; cvta.to.shared.u64 t, %1; cvt.u32.u64 %0, t; }"
        : "=r"(a) : "l"(p));
    return a;
}
__device__ __forceinline__ void cpa16(uint32_t s, const void* g) {
    asm volatile("cp.async.cg.shared.global [%0], [%1], 16;" :: "r"(s), "l"(g));
}
__device__ __forceinline__ void cpa_commit() {
    asm volatile("cp.async.commit_group;" ::: "memory");
}
template<int N> __device__ __forceinline__ void cpa_wait() {
    asm volatile("cp.async.wait_group %0;" :: "n"(N) : "memory");
}
__device__ __forceinline__ void ldsm4(uint32_t& r0, uint32_t& r1,
                                      uint32_t& r2, uint32_t& r3, uint32_t addr) {
    asm volatile("ldmatrix.sync.aligned.m8n8.x4.shared.b16 {%0,%1,%2,%3}, [%4];"
                 : "=r"(r0), "=r"(r1), "=r"(r2), "=r"(r3) : "r"(addr));
}
// f16 mma, fp32 accumulate
__device__ __forceinline__ void mma16(float* c, const uint32_t* a,
                                      uint32_t b0, uint32_t b1) {
    asm volatile(
        "mma.sync.aligned.m16n8k16.row.col.f32.f16.f16.f32 "
        "{%0,%1,%2,%3}, {%4,%5,%6,%7}, {%8,%9}, {%0,%1,%2,%3};"
        : "+f"(c[0]), "+f"(c[1]), "+f"(c[2]), "+f"(c[3])
        : "r"(a[0]), "r"(a[1]), "r"(a[2]), "r"(a[3]), "r"(b0), "r"(b1));
}

// FFMA-only exp
__device__ __forceinline__ float fast_exp(float x) {
    float t = x * 1.4426950408889634f;
    int   e = __float2int_rn(t);
    float f = t - (float)e;
    float p = 0.0013333558146428443f;
    p = fmaf(p, f, 0.009618129842126066f);
    p = fmaf(p, f, 0.05550410866482158f);
    p = fmaf(p, f, 0.2402265069591007f);
    p = fmaf(p, f, 0.6931471805599453f);
    p = fmaf(p, f, 1.0f);
    return p * __int_as_float((e + 127) << 23);
}

// ---------------------------------------------------------------------------
// fp32 -> fp16 (RN) pre-pass
// ---------------------------------------------------------------------------
__global__ void __launch_bounds__(256) cvt_f2h(const float* __restrict__ src,
                                               __half* __restrict__ dst, int n)
{
    int i = (blockIdx.x * 256 + threadIdx.x) * 4;
    if (i < n) {
        float4 v = *(const float4*)&src[i];
        __half2 lo = __floats2half2_rn(v.x, v.y);
        __half2 hi = __floats2half2_rn(v.z, v.w);
        *(__half2*)&dst[i]     = lo;
        *(__half2*)&dst[i + 2] = hi;
    }
}

// ---------------------------------------------------------------------------
// fp16 GEMM core: C[128x128] = A[128xK] @ Bw[128xK]^T (+Resid)
// 256 threads (8 warps, 2x4). Warp tile 64x32. BK=64 halves, 3-stage cp.async.
// SMEM stage: A 128x64h (16KB, swizzled 128B rows) | B 128x64h (16KB).
// ---------------------------------------------------------------------------
template<bool HALF_OUT, bool RES>
__device__ __forceinline__ void gemm_core(const __half* __restrict__ A,
                                          const __half* __restrict__ Bw,
                                          __half* __restrict__ Ch,
                                          float* __restrict__ Cf,
                                          const float* __restrict__ Resid,
                                          int m0, int n0, char* dsm)
{
    const uint32_t stg = smem_u32(dsm);
    const int tid = threadIdx.x;
    const int wid = tid >> 5, lane = tid & 31;
    const int wr = wid >> 2, wc = wid & 3;

    auto load_stage = [&](int kb) {
        uint32_t s = stg + (uint32_t)(kb % 3) * 32768u;
        int k0 = kb * 64;                  // in halves
#pragma unroll
        for (int i = 0; i < 8; i++) {
            int j     = tid + i * 256;     // 0..2047
            int which = j >> 10;           // 0:A 1:B
            int idx   = j & 1023;
            int r     = idx >> 3;          // 0..127
            int ch    = idx & 7;           // 16B chunk (8 halves)
            uint32_t dst = s + (uint32_t)which * 16384u
                         + (uint32_t)r * 128u + ((uint32_t)(ch ^ (r & 7)) << 4);
            const __half* src = which ? &Bw[(size_t)(n0 + r) * Ee + k0 + ch * 8]
                                      : &A [(size_t)(m0 + r) * Ee + k0 + ch * 8];
            cpa16(dst, src);
        }
        cpa_commit();
    };

    float acc[4][4][4];
#pragma unroll
    for (int i = 0; i < 4; i++)
#pragma unroll
        for (int j = 0; j < 4; j++)
#pragma unroll
            for (int k = 0; k < 4; k++) acc[i][j][k] = 0.f;

    load_stage(0); load_stage(1);

    // A frag addressing (m16n8k16, x4 ldsm): row = base + lane%16, kchunk += lane/16
    const int rA = wr * 64 + (lane & 15);
    const int cAadd = lane >> 4;                    // 0/1
    // B frag addressing: row(n) = base + lane%8 + (lane/16)*8, kchunk += (lane>>3)&1
    const int rB = wc * 32 + (lane & 7) + ((lane >> 4) << 3);
    const int cBadd = (lane >> 3) & 1;

    for (int kb = 0; kb < 16; ++kb) {
        if (kb + 2 < 16) cpa_wait<1>(); else cpa_wait<0>();
        __syncthreads();
        if (kb + 2 < 16) load_stage(kb + 2);

        uint32_t As = stg + (uint32_t)(kb % 3) * 32768u;
        uint32_t Bs = As + 16384u;
#pragma unroll
        for (int ks = 0; ks < 4; ++ks) {            // 4 x k16
            uint32_t a[4][4];
#pragma unroll
            for (int mi = 0; mi < 4; mi++) {
                int row = rA + mi * 16;
                int ch  = 2 * ks + cAadd;
                uint32_t addr = As + (uint32_t)row * 128u
                              + ((uint32_t)(ch ^ (row & 7)) << 4);
                ldsm4(a[mi][0], a[mi][1], a[mi][2], a[mi][3], addr);
            }
            uint32_t b[2][4];
#pragma unroll
            for (int njp = 0; njp < 2; njp++) {
                int row = rB + njp * 16;
                int ch  = 2 * ks + cBadd;
                uint32_t addr = Bs + (uint32_t)row * 128u
                              + ((uint32_t)(ch ^ (row & 7)) << 4);
                ldsm4(b[njp][0], b[njp][1], b[njp][2], b[njp][3], addr);
            }
#pragma unroll
            for (int mi = 0; mi < 4; mi++)
#pragma unroll
                for (int nj = 0; nj < 4; nj++)
                    mma16(acc[mi][nj], a[mi],
                          b[nj >> 1][(nj & 1) * 2], b[nj >> 1][(nj & 1) * 2 + 1]);
        }
    }

    // epilogue: c0:(g,2t) c1:(g,2t+1) c2:(g+8,2t) c3:(g+8,2t+1)
#pragma unroll
    for (int mi = 0; mi < 4; mi++) {
        int r0 = m0 + wr * 64 + mi * 16 + (lane >> 2);
#pragma unroll
        for (int nj = 0; nj < 4; nj++) {
            int c0 = n0 + wc * 32 + nj * 8 + 2 * (lane & 3);
            if (HALF_OUT) {
                *(__half2*)&Ch[(size_t)r0 * Ee + c0] =
                    __floats2half2_rn(acc[mi][nj][0], acc[mi][nj][1]);
                *(__half2*)&Ch[(size_t)(r0 + 8) * Ee + c0] =
                    __floats2half2_rn(acc[mi][nj][2], acc[mi][nj][3]);
            } else {
                float2 v0 = {acc[mi][nj][0], acc[mi][nj][1]};
                float2 v1 = {acc[mi][nj][2], acc[mi][nj][3]};
                if (RES) {
                    float2 a0 = *(const float2*)&Resid[(size_t)r0 * Ee + c0];
                    float2 a1 = *(const float2*)&Resid[(size_t)(r0 + 8) * Ee + c0];
                    v0.x += a0.x; v0.y += a0.y; v1.x += a1.x; v1.y += a1.y;
                }
                *(float2*)&Cf[(size_t)r0 * Ee + c0]       = v0;
                *(float2*)&Cf[(size_t)(r0 + 8) * Ee + c0] = v1;
            }
        }
    }
}

__global__ void __launch_bounds__(256, 2)
tc_qkv()
{
    extern __shared__ char dsm[];
    int z = blockIdx.z;
    const __half* W = (z == 0) ? g_wqh : (z == 1) ? g_wkh : g_wvh;
    if (z == 2)
        gemm_core<false, false>(g_xh, W, nullptr, g_v, nullptr,
                                blockIdx.y * 128, blockIdx.x * 128, dsm);
    else
        gemm_core<true, false>(g_xh, W, (z == 0) ? g_qh : g_kh, nullptr, nullptr,
                               blockIdx.y * 128, blockIdx.x * 128, dsm);
}

__global__ void __launch_bounds__(256, 2)
tc_out(float* __restrict__ Out)
{
    extern __shared__ char dsm[];
    gemm_core<false, true>(g_avh, g_woh, nullptr, Out, g_v,
                           blockIdx.y * 128, blockIdx.x * 128, dsm);
}

// ---------------------------------------------------------------------------
// Score pass (fp16 q,k): per (b,h,qtile=128): S = Q[128x64] @ K[128x64]^T,
// exp + causal row sums in registers; gate g = diag / rowsum.
// 256 threads, 8 warps (2x4), warp tile 64x32. SMEM: Q 16KB + 3 K x 16KB.
// ---------------------------------------------------------------------------
__global__ void __launch_bounds__(256, 2)
tc_score()
{
    extern __shared__ char dsm[];
    const uint32_t Qs = smem_u32(dsm);
    const uint32_t Ks = Qs + 16384u;
    float* sSum  = (float*)(dsm + 16384 + 3 * 16384);
    float* sDiag = sSum + 128;

    const int qt = blockIdx.x, h = blockIdx.y, b = blockIdx.z;
    const int tid = threadIdx.x;
    const int wid = tid >> 5, lane = tid & 31;
    const int wr = wid >> 2, wc = wid & 3;

    auto load_q = [&]() {
#pragma unroll
        for (int i = 0; i < 4; i++) {
            int j  = tid + i * 256;     // 0..1023
            int r  = j >> 3;            // 0..127
            int ch = j & 7;             // 8 chunks (64 halves/row)
            uint32_t dst = Qs + (uint32_t)r * 128u + ((uint32_t)(ch ^ (r & 7)) << 4);
            cpa16(dst, &g_qh[(size_t)(b * Ss + qt * 128 + r) * Ee + h * Dd + ch * 8]);
        }
    };
    auto load_k = [&](int kt, int slot) {
        uint32_t s = Ks + (uint32_t)slot * 16384u;
#pragma unroll
        for (int i = 0; i < 4; i++) {
            int j  = tid + i * 256;
            int r  = j >> 3;
            int ch = j & 7;
            uint32_t dst = s + (uint32_t)r * 128u + ((uint32_t)(ch ^ (r & 7)) << 4);
            cpa16(dst, &g_kh[(size_t)(b * Ss + kt * 128 + r) * Ee + h * Dd + ch * 8]);
        }
    };

    load_q(); load_k(0, 0); cpa_commit();
    if (qt >= 1) { load_k(1, 1); cpa_commit(); }

    if (tid < 128) { sSum[tid] = 0.f; sDiag[tid] = 0.f; }

    float rs[8], dv[8];
#pragma unroll
    for (int k = 0; k < 8; k++) { rs[k] = 0.f; dv[k] = 0.f; }

    const int rA = wr * 64 + (lane & 15);
    const int cAadd = lane >> 4;
    const int rB = wc * 32 + (lane & 7) + ((lane >> 4) << 3);
    const int cBadd = (lane >> 3) & 1;

    for (int kt = 0; kt <= qt; ++kt) {
        if (kt == qt) cpa_wait<0>(); else cpa_wait<1>();
        __syncthreads();
        if (kt + 2 <= qt) { load_k(kt + 2, (kt + 2) % 3); cpa_commit(); }

        float acc[4][4][4];
#pragma unroll
        for (int i = 0; i < 4; i++)
#pragma unroll
            for (int j = 0; j < 4; j++)
#pragma unroll
                for (int k = 0; k < 4; k++) acc[i][j][k] = 0.f;

        uint32_t Ksl = Ks + (uint32_t)(kt % 3) * 16384u;
#pragma unroll
        for (int ks = 0; ks < 4; ++ks) {
            uint32_t a[4][4];
#pragma unroll
            for (int mi = 0; mi < 4; mi++) {
                int row = rA + mi * 16;
                int ch  = 2 * ks + cAadd;
                uint32_t addr = Qs + (uint32_t)row * 128u
                              + ((uint32_t)(ch ^ (row & 7)) << 4);
                ldsm4(a[mi][0], a[mi][1], a[mi][2], a[mi][3], addr);
            }
            uint32_t bfr[2][4];
#pragma unroll
            for (int njp = 0; njp < 2; njp++) {
                int row = rB + njp * 16;
                int ch  = 2 * ks + cBadd;
                uint32_t addr = Ksl + (uint32_t)row * 128u
                              + ((uint32_t)(ch ^ (row & 7)) << 4);
                ldsm4(bfr[njp][0], bfr[njp][1], bfr[njp][2], bfr[njp][3], addr);
            }
#pragma unroll
            for (int mi = 0; mi < 4; mi++)
#pragma unroll
                for (int nj = 0; nj < 4; nj++)
                    mma16(acc[mi][nj], a[mi],
                          bfr[nj >> 1][(nj & 1) * 2], bfr[nj >> 1][(nj & 1) * 2 + 1]);
        }

        const bool dt = (kt == qt);
#pragma unroll
        for (int mi = 0; mi < 4; mi++) {
            int il0 = wr * 64 + mi * 16 + (lane >> 2);
#pragma unroll
            for (int nj = 0; nj < 4; nj++) {
                int jl = wc * 32 + nj * 8 + 2 * (lane & 3);
#pragma unroll
                for (int q = 0; q < 4; q++) {
                    int il = il0 + (q >> 1) * 8;
                    int j  = jl  + (q & 1);
                    float e = fast_exp(acc[mi][nj][q] * 0.03125f);
                    if (dt) {
                        if (j > il)  e = 0.f;
                        if (j == il) dv[mi * 2 + (q >> 1)] = e;
                    }
                    rs[mi * 2 + (q >> 1)] += e;
                }
            }
        }
    }

    // quad reduce (lanes in a quad share rows), then cross-warp via smem atomics
#pragma unroll
    for (int k = 0; k < 8; k++) {
        rs[k] += __shfl_xor_sync(0xffffffffu, rs[k], 1);
        rs[k] += __shfl_xor_sync(0xffffffffu, rs[k], 2);
        dv[k] += __shfl_xor_sync(0xffffffffu, dv[k], 1);
        dv[k] += __shfl_xor_sync(0xffffffffu, dv[k], 2);
    }
    if ((lane & 3) == 0) {
#pragma unroll
        for (int k = 0; k < 8; k++) {
            int row = wr * 64 + (k >> 1) * 16 + (k & 1) * 8 + (lane >> 2);
            atomicAdd(&sSum[row], rs[k]);
            atomicAdd(&sDiag[row], dv[k]);
        }
    }
    __syncthreads();
    if (tid < 128)
        g_g[((size_t)b * Hh + h) * Ss + qt * 128 + tid] = sDiag[tid] / sSum[tid];
}

// ---------------------------------------------------------------------------
// gv = g ⊙ v  -> fp16 (A operand of the out-GEMM)
// ---------------------------------------------------------------------------
__global__ void __launch_bounds__(256) gv_prep()
{
    int row = blockIdx.x;
    int tid = threadIdx.x;
    int b = row >> 11, s = row & 2047;
    int h = tid >> 4;
    float gval = g_g[((size_t)(b * Hh + h)) * Ss + s];
    float4 v = *(const float4*)&g_v[(size_t)row * Ee + tid * 4];
    __half2 lo = __floats2half2_rn(v.x * gval, v.y * gval);
    __half2 hi = __floats2half2_rn(v.z * gval, v.w * gval);
    *(__half2*)&g_avh[(size_t)row * Ee + tid * 4]     = lo;
    *(__half2*)&g_avh[(size_t)row * Ee + tid * 4 + 2] = hi;
}

// ---------------------------------------------------------------------------
extern "C" void kernel_launch(void* const* d_in, const int* in_sizes, int n_in,
                              void* d_out, int out_size)
{
    const float* x  = (const float*)d_in[0];
    const float* wq = (const float*)d_in[1];
    const float* wk = (const float*)d_in[2];
    const float* wv = (const float*)d_in[3];
    const float* wo = (const float*)d_in[4];
    float* out = (float*)d_out;

    const int SMEM_GEMM  = 3 * 32768;                 // 96 KB
    const int SMEM_SCORE = 16384 + 3 * 16384 + 1024;  // 64 KB + reduce

    cudaFuncSetAttribute(tc_qkv,   cudaFuncAttributeMaxDynamicSharedMemorySize, SMEM_GEMM);
    cudaFuncSetAttribute(tc_out,   cudaFuncAttributeMaxDynamicSharedMemorySize, SMEM_GEMM);
    cudaFuncSetAttribute(tc_score, cudaFuncAttributeMaxDynamicSharedMemorySize, SMEM_SCORE);

    // fp32 -> fp16 RN pre-pass (fixes truncation bias once, outside hot loops)
    __half* xh;  cudaGetSymbolAddress((void**)&xh,  g_xh);
    __half* wqh; cudaGetSymbolAddress((void**)&wqh, g_wqh);
    __half* wkh; cudaGetSymbolAddress((void**)&wkh, g_wkh);
    __half* wvh; cudaGetSymbolAddress((void**)&wvh, g_wvh);
    __half* woh; cudaGetSymbolAddress((void**)&woh, g_woh);
    cvt_f2h<<<(Mm * Ee / 4 + 255) / 256, 256>>>(x,  xh,  Mm * Ee);
    cvt_f2h<<<(Ee * Ee / 4 + 255) / 256, 256>>>(wq, wqh, Ee * Ee);
    cvt_f2h<<<(Ee * Ee / 4 + 255) / 256, 256>>>(wk, wkh, Ee * Ee);
    cvt_f2h<<<(Ee * Ee / 4 + 255) / 256, 256>>>(wv, wvh, Ee * Ee);
    cvt_f2h<<<(Ee * Ee / 4 + 255) / 256, 256>>>(wo, woh, Ee * Ee);

    tc_qkv<<<dim3(Ee / 128, Mm / 128, 3), 256, SMEM_GEMM>>>();
    tc_score<<<dim3(Ss / 128, Hh, Bb), 256, SMEM_SCORE>>>();
    gv_prep<<<Mm, 256>>>();
    tc_out<<<dim3(Ee / 128, Mm / 128), 256, SMEM_GEMM>>>(out);
}